// round 7
// baseline (speedup 1.0000x reference)
#include <cuda_runtime.h>
#include <math.h>

// Problem constants
#define BN_TOTAL 16384          // B*N = 16*1024
#define BND      4194304        // B*N*D = 16384*256
#define P_SEG    20             // M-1 segments
#define D_OUT    256

// Packed fp32x2 helpers (Blackwell FFMA2 path — only reachable via PTX)
#define FMA2(d, a, b) \
    asm("fma.rn.f32x2 %0, %1, %2, %0;" : "+l"(d) : "l"(a), "l"(b))
#define PACK2(d, lo, hi) \
    asm("mov.b64 %0, {%1, %2};" : "=l"(d) : "f"(lo), "f"(hi))
#define UNPACK2(lo, hi, d) \
    asm("mov.b64 {%0, %1}, %2;" : "=f"(lo), "=f"(hi) : "l"(d))

typedef unsigned long long u64;

// Shared memory layout (floats):
//  s_h1   : 20*128 = 2560
//  s_h    : 20*256 = 5120
//  s_h2   : 20*256 = 5120
//  s_pool : 256
//  s_sine : 256
//  s_pe1  : 512
//  s_feat : 20*6 = 120
#define SMEM_FLOATS (2560 + 5120 + 5120 + 256 + 256 + 512 + 120)

__global__ __launch_bounds__(256, 2)
void map_encoder_kernel(const float* __restrict__ tgt,      // (16384, 21, 2)
                        const int*   __restrict__ label,    // (16384)
                        const unsigned int* __restrict__ mask, // (16384) bool as 32-bit (int32 OR float32 — nonzero test covers both)
                        const float* __restrict__ W1, const float* __restrict__ b1,
                        const float* __restrict__ g1, const float* __restrict__ be1,
                        const float* __restrict__ m1, const float* __restrict__ v1,
                        const float* __restrict__ W2, const float* __restrict__ b2,
                        const float* __restrict__ W3, const float* __restrict__ b3,
                        const float* __restrict__ g2, const float* __restrict__ be2,
                        const float* __restrict__ m2, const float* __restrict__ v2,
                        const float* __restrict__ W4, const float* __restrict__ b4,
                        const float* __restrict__ temb,
                        const float* __restrict__ Wp1, const float* __restrict__ bp1,
                        const float* __restrict__ Wp2, const float* __restrict__ bp2,
                        const float* __restrict__ pcr,
                        float* __restrict__ out)
{
    extern __shared__ float sm[];
    float* s_h1   = sm;                 // 2560
    float* s_h    = s_h1 + 2560;        // 5120
    float* s_h2   = s_h  + 5120;        // 5120
    float* s_pool = s_h2 + 5120;        // 256
    float* s_sine = s_pool + 256;       // 256
    float* s_pe1  = s_sine + 256;       // 512
    float* s_feat = s_pe1 + 512;        // 120

    const int idx = blockIdx.x;
    const int tid = threadIdx.x;

    float* outF = out + (size_t)idx * D_OUT;            // map_feats row
    float* outP = out + BND + (size_t)idx * D_OUT;      // x_pos row

    const bool mk = (mask[idx] != 0u);   // raw 32-bit nonzero: works for int32 0/1 and float32 0.0/1.0
    if (!mk) {
        // masked-out polyline: everything is exactly zero; ~mask = 1
        outF[tid] = 0.0f;
        outP[tid] = 0.0f;
        if (tid == 0) out[2 * (size_t)BND + idx] = 1.0f;
        return;
    }
    if (tid == 0) out[2 * (size_t)BND + idx] = 0.0f;

    const float* pts = tgt + (size_t)idx * 42;   // 21 points * 2

    // ---------------- Stage A: per-segment features (20 x 6) ----------------
    if (tid < P_SEG) {
        float x0 = pts[2*tid],   y0 = pts[2*tid+1];
        float x1 = pts[2*tid+2], y1 = pts[2*tid+3];
        float cx = pts[20], cy = pts[21];           // center = point 10
        float pvx = x1 - x0, pvy = y1 - y0;
        float vn = sqrtf(pvx*pvx + pvy*pvy) + 1.0f + 1e-6f;  // + mask(=1) + 1e-6
        float inv = 1.0f / vn;
        float* f = s_feat + tid * 6;
        f[0] = x0 - cx; f[1] = y0 - cy;
        f[2] = pvx;     f[3] = pvy;
        f[4] = pvx * inv; f[5] = pvy * inv;
    }
    __syncthreads();

    // ---------------- Stage B: h1 = relu(BN1(feat @ W1 + b1)) -> (20,128) ---
    {
        const int d = tid & 127;
        float w0 = W1[d],       w1 = W1[128 + d], w2 = W1[256 + d];
        float w3 = W1[384 + d], w4 = W1[512 + d], w5 = W1[640 + d];
        float a1 = rsqrtf(v1[d] + 1e-5f) * g1[d];
        float c1 = be1[d] - m1[d] * a1;
        float bb = b1[d];
        const int p0 = tid >> 7;
        #pragma unroll
        for (int i = 0; i < 10; i++) {
            int p = p0 + 2 * i;
            const float* f = s_feat + p * 6;
            float t = bb + f[0]*w0 + f[1]*w1 + f[2]*w2 + f[3]*w3 + f[4]*w4 + f[5]*w5;
            t = t * a1 + c1;
            s_h1[p * 128 + d] = fmaxf(t, 0.0f);
        }
    }
    __syncthreads();

    const int e = tid;
    u64 acc2[P_SEG];

    // ---------------- Stage C: h = h1 @ W2 + b2 -> (20,256); pooled max -----
    {
        u64 binit; PACK2(binit, b2[e], 0.0f);
        #pragma unroll
        for (int p = 0; p < P_SEG; p++) acc2[p] = binit;
        for (int k = 0; k < 128; k += 4) {
            float w0 = W2[(k+0)*256 + e];
            float w1 = W2[(k+1)*256 + e];
            float w2 = W2[(k+2)*256 + e];
            float w3 = W2[(k+3)*256 + e];
            u64 w01, w23; PACK2(w01, w0, w1); PACK2(w23, w2, w3);
            #pragma unroll
            for (int p = 0; p < P_SEG; p++) {
                ulonglong2 h = *reinterpret_cast<const ulonglong2*>(s_h1 + p*128 + k);
                FMA2(acc2[p], h.x, w01);
                FMA2(acc2[p], h.y, w23);
            }
        }
        float pm = -3.402823466e38f;
        #pragma unroll
        for (int p = 0; p < P_SEG; p++) {
            float lo, hi; UNPACK2(lo, hi, acc2[p]);
            float v = lo + hi;
            s_h[p*256 + e] = v;
            pm = fmaxf(pm, v);
        }
        s_pool[e] = pm;
    }
    __syncthreads();

    // ---------------- Stage D: h2a = relu(BN2(cat @ W3 + b3)) ---------------
    // cat = [h | pooled] ; pooled half identical for every p -> compute once.
    {
        u64 sacc; PACK2(sacc, b3[e], 0.0f);
        for (int k = 0; k < 256; k += 4) {
            ulonglong2 pv = *reinterpret_cast<const ulonglong2*>(s_pool + k);
            float w0 = W3[(256 + k + 0)*256 + e];
            float w1 = W3[(256 + k + 1)*256 + e];
            float w2 = W3[(256 + k + 2)*256 + e];
            float w3 = W3[(256 + k + 3)*256 + e];
            u64 w01, w23; PACK2(w01, w0, w1); PACK2(w23, w2, w3);
            FMA2(sacc, pv.x, w01);
            FMA2(sacc, pv.y, w23);
        }
        #pragma unroll
        for (int p = 0; p < P_SEG; p++) acc2[p] = sacc;
        for (int k = 0; k < 256; k += 4) {
            float w0 = W3[(k+0)*256 + e];
            float w1 = W3[(k+1)*256 + e];
            float w2 = W3[(k+2)*256 + e];
            float w3 = W3[(k+3)*256 + e];
            u64 w01, w23; PACK2(w01, w0, w1); PACK2(w23, w2, w3);
            #pragma unroll
            for (int p = 0; p < P_SEG; p++) {
                ulonglong2 h = *reinterpret_cast<const ulonglong2*>(s_h + p*256 + k);
                FMA2(acc2[p], h.x, w01);
                FMA2(acc2[p], h.y, w23);
            }
        }
        float a2 = rsqrtf(v2[e] + 1e-5f) * g2[e];
        float c2 = be2[e] - m2[e] * a2;
        #pragma unroll
        for (int p = 0; p < P_SEG; p++) {
            float lo, hi; UNPACK2(lo, hi, acc2[p]);
            s_h2[p*256 + e] = fmaxf((lo + hi) * a2 + c2, 0.0f);
        }
    }
    __syncthreads();

    // ---------------- Stage E: h2 = h2a @ W4 + b4; maxpool + type_emb -------
    {
        u64 binit; PACK2(binit, b4[e], 0.0f);
        #pragma unroll
        for (int p = 0; p < P_SEG; p++) acc2[p] = binit;
        for (int k = 0; k < 256; k += 4) {
            float w0 = W4[(k+0)*256 + e];
            float w1 = W4[(k+1)*256 + e];
            float w2 = W4[(k+2)*256 + e];
            float w3 = W4[(k+3)*256 + e];
            u64 w01, w23; PACK2(w01, w0, w1); PACK2(w23, w2, w3);
            #pragma unroll
            for (int p = 0; p < P_SEG; p++) {
                ulonglong2 h = *reinterpret_cast<const ulonglong2*>(s_h2 + p*256 + k);
                FMA2(acc2[p], h.x, w01);
                FMA2(acc2[p], h.y, w23);
            }
        }
        float xp = -3.402823466e38f;
        #pragma unroll
        for (int p = 0; p < P_SEG; p++) {
            float lo, hi; UNPACK2(lo, hi, acc2[p]);
            xp = fmaxf(xp, lo + hi);
        }
        xp += temb[label[idx] * 256 + e];
        outF[e] = xp;
    }

    // ---------------- Stage F: sine embedding of normalized center ----------
    {
        float cx = pts[20], cy = pts[21];
        float posv = (tid < 128) ? (cy - pcr[1]) / (pcr[4] - pcr[1])
                                 : (cx - pcr[0]) / (pcr[3] - pcr[0]);
        int il = tid & 127;
        int j  = il >> 1;
        // dim_t = 10000^(j/64); t = pos * 2pi / dim_t
        float t = posv * 6.283185307179586f * exp2f(-0.20762050593046014f * (float)j);
        s_sine[tid] = (il & 1) ? cosf(t) : sinf(t);
    }
    __syncthreads();

    // pe1 = relu(sine @ Wp1 + bp1)  -> 512 (2 outputs per thread)
    {
        u64 a0; PACK2(a0, bp1[tid], 0.0f);
        u64 a1; PACK2(a1, bp1[tid + 256], 0.0f);
        for (int k = 0; k < 256; k += 4) {
            ulonglong2 sv = *reinterpret_cast<const ulonglong2*>(s_sine + k);
            float x0 = Wp1[(k+0)*512 + tid];
            float x1 = Wp1[(k+1)*512 + tid];
            float x2 = Wp1[(k+2)*512 + tid];
            float x3 = Wp1[(k+3)*512 + tid];
            float y0 = Wp1[(k+0)*512 + tid + 256];
            float y1 = Wp1[(k+1)*512 + tid + 256];
            float y2 = Wp1[(k+2)*512 + tid + 256];
            float y3 = Wp1[(k+3)*512 + tid + 256];
            u64 wx01, wx23, wy01, wy23;
            PACK2(wx01, x0, x1); PACK2(wx23, x2, x3);
            PACK2(wy01, y0, y1); PACK2(wy23, y2, y3);
            FMA2(a0, sv.x, wx01); FMA2(a0, sv.y, wx23);
            FMA2(a1, sv.x, wy01); FMA2(a1, sv.y, wy23);
        }
        float lo, hi;
        UNPACK2(lo, hi, a0); s_pe1[tid]       = fmaxf(lo + hi, 0.0f);
        UNPACK2(lo, hi, a1); s_pe1[tid + 256] = fmaxf(lo + hi, 0.0f);
    }
    __syncthreads();

    // pe = pe1 @ Wp2 + bp2 -> 256
    {
        u64 a0; PACK2(a0, bp2[tid], 0.0f);
        for (int k = 0; k < 512; k += 4) {
            ulonglong2 pv = *reinterpret_cast<const ulonglong2*>(s_pe1 + k);
            float w0 = Wp2[(k+0)*256 + tid];
            float w1 = Wp2[(k+1)*256 + tid];
            float w2 = Wp2[(k+2)*256 + tid];
            float w3 = Wp2[(k+3)*256 + tid];
            u64 w01, w23; PACK2(w01, w0, w1); PACK2(w23, w2, w3);
            FMA2(a0, pv.x, w01);
            FMA2(a0, pv.y, w23);
        }
        float lo, hi; UNPACK2(lo, hi, a0);
        outP[tid] = lo + hi;
    }
}

extern "C" void kernel_launch(void* const* d_in, const int* in_sizes, int n_in,
                              void* d_out, int out_size)
{
    const float*        tgt   = (const float*)d_in[0];
    const int*          label = (const int*)d_in[1];
    const unsigned int* mask  = (const unsigned int*)d_in[2];  // bool arrives as 32-bit (int32/float32)
    const float* W1  = (const float*)d_in[3];
    const float* b1  = (const float*)d_in[4];
    const float* g1  = (const float*)d_in[5];
    const float* be1 = (const float*)d_in[6];
    const float* m1  = (const float*)d_in[7];
    const float* v1  = (const float*)d_in[8];
    const float* W2  = (const float*)d_in[9];
    const float* b2  = (const float*)d_in[10];
    const float* W3  = (const float*)d_in[11];
    const float* b3  = (const float*)d_in[12];
    const float* g2  = (const float*)d_in[13];
    const float* be2 = (const float*)d_in[14];
    const float* m2  = (const float*)d_in[15];
    const float* v2  = (const float*)d_in[16];
    const float* W4  = (const float*)d_in[17];
    const float* b4  = (const float*)d_in[18];
    const float* te  = (const float*)d_in[19];
    const float* Wp1 = (const float*)d_in[20];
    const float* bp1 = (const float*)d_in[21];
    const float* Wp2 = (const float*)d_in[22];
    const float* bp2 = (const float*)d_in[23];
    const float* pcr = (const float*)d_in[24];
    float* out = (float*)d_out;

    const size_t smem = SMEM_FLOATS * sizeof(float);  // 55,776 B > 48KB default
    cudaFuncSetAttribute(map_encoder_kernel,
                         cudaFuncAttributeMaxDynamicSharedMemorySize, (int)smem);

    map_encoder_kernel<<<BN_TOTAL, 256, smem>>>(
        tgt, label, mask,
        W1, b1, g1, be1, m1, v1,
        W2, b2, W3, b3, g2, be2, m2, v2,
        W4, b4, te, Wp1, bp1, Wp2, bp2, pcr, out);
}

// round 8
// speedup vs baseline: 1.4789x; 1.4789x over previous
#include <cuda_runtime.h>
#include <math.h>

#define BN_TOTAL 16384          // B*N
#define BND      4194304        // B*N*256
#define P_SEG    20
#define D_OUT    256

// Packed fp32x2 (Blackwell FFMA2 — PTX-only path)
#define FMA2(d, a, b) \
    asm("fma.rn.f32x2 %0, %1, %2, %0;" : "+l"(d) : "l"(a), "l"(b))
#define PACK2(d, lo, hi) \
    asm("mov.b64 %0, {%1, %2};" : "=l"(d) : "f"(lo), "f"(hi))
#define UNPACK2(lo, hi, d) \
    asm("mov.b64 {%0, %1}, %2;" : "=f"(lo), "=f"(hi) : "l"(d))

typedef unsigned long long u64;

// ---------------- Kernel 1: encoder stages A-E (no PE MLP) ------------------
// 128 threads; thread t owns output columns t and t+128  -> each broadcast
// LDS.128 feeds 4 FFMA2 (halves LDS wavefronts vs 1 col/thread).
// smem floats: s_h1 2560 | s_h 5120 | s_h2 5120 | s_pool 256 | s_feat 120
#define K1_SMEM_FLOATS (2560 + 5120 + 5120 + 256 + 120)

__global__ __launch_bounds__(128, 3)
void map_encoder_main(const float* __restrict__ tgt,
                      const int*   __restrict__ label,
                      const unsigned int* __restrict__ mask,   // bool as 32-bit
                      const float* __restrict__ W1, const float* __restrict__ b1,
                      const float* __restrict__ g1, const float* __restrict__ be1,
                      const float* __restrict__ m1, const float* __restrict__ v1,
                      const float* __restrict__ W2, const float* __restrict__ b2,
                      const float* __restrict__ W3, const float* __restrict__ b3,
                      const float* __restrict__ g2, const float* __restrict__ be2,
                      const float* __restrict__ m2, const float* __restrict__ v2,
                      const float* __restrict__ W4, const float* __restrict__ b4,
                      const float* __restrict__ temb,
                      float* __restrict__ out)
{
    extern __shared__ float sm[];
    float* s_h1   = sm;                 // 2560
    float* s_h    = s_h1 + 2560;        // 5120
    float* s_h2   = s_h  + 5120;        // 5120
    float* s_pool = s_h2 + 5120;        // 256
    float* s_feat = s_pool + 256;       // 120

    const int idx = blockIdx.x;
    const int t   = threadIdx.x;
    const int c0  = t;
    const int c1  = t + 128;

    float* outF = out + (size_t)idx * D_OUT;

    const bool mk = (mask[idx] != 0u);
    if (!mk) {
        outF[c0] = 0.0f;
        outF[c1] = 0.0f;
        if (t == 0) out[2 * (size_t)BND + idx] = 1.0f;
        return;
    }
    if (t == 0) out[2 * (size_t)BND + idx] = 0.0f;

    const float* pts = tgt + (size_t)idx * 42;

    // Stage A: per-segment features (20 x 6)
    if (t < P_SEG) {
        float x0 = pts[2*t],   y0 = pts[2*t+1];
        float x1 = pts[2*t+2], y1 = pts[2*t+3];
        float cx = pts[20], cy = pts[21];
        float pvx = x1 - x0, pvy = y1 - y0;
        float vn = sqrtf(pvx*pvx + pvy*pvy) + 1.0f + 1e-6f;
        float inv = 1.0f / vn;
        float* f = s_feat + t * 6;
        f[0] = x0 - cx; f[1] = y0 - cy;
        f[2] = pvx;     f[3] = pvy;
        f[4] = pvx * inv; f[5] = pvy * inv;
    }
    __syncthreads();

    // Stage B: h1 = relu(BN1(feat @ W1 + b1)) -> (20,128); thread t owns d=t
    {
        const int d = t;
        float w0 = W1[d],       w1 = W1[128 + d], w2 = W1[256 + d];
        float w3 = W1[384 + d], w4 = W1[512 + d], w5 = W1[640 + d];
        float a1 = rsqrtf(v1[d] + 1e-5f) * g1[d];
        float cc = be1[d] - m1[d] * a1;
        float bb = b1[d];
        #pragma unroll
        for (int p = 0; p < P_SEG; p++) {
            const float* f = s_feat + p * 6;
            float s = bb + f[0]*w0 + f[1]*w1 + f[2]*w2 + f[3]*w3 + f[4]*w4 + f[5]*w5;
            s = s * a1 + cc;
            s_h1[p * 128 + d] = fmaxf(s, 0.0f);
        }
    }
    __syncthreads();

    u64 accA[P_SEG], accB[P_SEG];

    // Stage C: h = h1 @ W2 + b2 -> (20,256); pooled max
    {
        u64 biA, biB; PACK2(biA, b2[c0], 0.0f); PACK2(biB, b2[c1], 0.0f);
        #pragma unroll
        for (int p = 0; p < P_SEG; p++) { accA[p] = biA; accB[p] = biB; }
        for (int k = 0; k < 128; k += 4) {
            float a0 = W2[(k+0)*256 + c0], a1w = W2[(k+1)*256 + c0];
            float a2 = W2[(k+2)*256 + c0], a3 = W2[(k+3)*256 + c0];
            float q0 = W2[(k+0)*256 + c1], q1 = W2[(k+1)*256 + c1];
            float q2 = W2[(k+2)*256 + c1], q3 = W2[(k+3)*256 + c1];
            u64 wa01, wa23, wb01, wb23;
            PACK2(wa01, a0, a1w); PACK2(wa23, a2, a3);
            PACK2(wb01, q0, q1);  PACK2(wb23, q2, q3);
            #pragma unroll
            for (int p = 0; p < P_SEG; p++) {
                ulonglong2 h = *reinterpret_cast<const ulonglong2*>(s_h1 + p*128 + k);
                FMA2(accA[p], h.x, wa01); FMA2(accA[p], h.y, wa23);
                FMA2(accB[p], h.x, wb01); FMA2(accB[p], h.y, wb23);
            }
        }
        float pmA = -3.402823466e38f, pmB = -3.402823466e38f;
        #pragma unroll
        for (int p = 0; p < P_SEG; p++) {
            float lo, hi, vA, vB;
            UNPACK2(lo, hi, accA[p]); vA = lo + hi;
            UNPACK2(lo, hi, accB[p]); vB = lo + hi;
            s_h[p*256 + c0] = vA; s_h[p*256 + c1] = vB;
            pmA = fmaxf(pmA, vA); pmB = fmaxf(pmB, vB);
        }
        s_pool[c0] = pmA; s_pool[c1] = pmB;
    }
    __syncthreads();

    // Stage D: h2a = relu(BN2(cat @ W3 + b3)); pooled half computed once
    {
        u64 sA, sB; PACK2(sA, b3[c0], 0.0f); PACK2(sB, b3[c1], 0.0f);
        for (int k = 0; k < 256; k += 4) {
            ulonglong2 pv = *reinterpret_cast<const ulonglong2*>(s_pool + k);
            float a0 = W3[(256+k+0)*256 + c0], a1w = W3[(256+k+1)*256 + c0];
            float a2 = W3[(256+k+2)*256 + c0], a3 = W3[(256+k+3)*256 + c0];
            float q0 = W3[(256+k+0)*256 + c1], q1 = W3[(256+k+1)*256 + c1];
            float q2 = W3[(256+k+2)*256 + c1], q3 = W3[(256+k+3)*256 + c1];
            u64 wa01, wa23, wb01, wb23;
            PACK2(wa01, a0, a1w); PACK2(wa23, a2, a3);
            PACK2(wb01, q0, q1);  PACK2(wb23, q2, q3);
            FMA2(sA, pv.x, wa01); FMA2(sA, pv.y, wa23);
            FMA2(sB, pv.x, wb01); FMA2(sB, pv.y, wb23);
        }
        #pragma unroll
        for (int p = 0; p < P_SEG; p++) { accA[p] = sA; accB[p] = sB; }
        for (int k = 0; k < 256; k += 4) {
            float a0 = W3[(k+0)*256 + c0], a1w = W3[(k+1)*256 + c0];
            float a2 = W3[(k+2)*256 + c0], a3 = W3[(k+3)*256 + c0];
            float q0 = W3[(k+0)*256 + c1], q1 = W3[(k+1)*256 + c1];
            float q2 = W3[(k+2)*256 + c1], q3 = W3[(k+3)*256 + c1];
            u64 wa01, wa23, wb01, wb23;
            PACK2(wa01, a0, a1w); PACK2(wa23, a2, a3);
            PACK2(wb01, q0, q1);  PACK2(wb23, q2, q3);
            #pragma unroll
            for (int p = 0; p < P_SEG; p++) {
                ulonglong2 h = *reinterpret_cast<const ulonglong2*>(s_h + p*256 + k);
                FMA2(accA[p], h.x, wa01); FMA2(accA[p], h.y, wa23);
                FMA2(accB[p], h.x, wb01); FMA2(accB[p], h.y, wb23);
            }
        }
        float aA = rsqrtf(v2[c0] + 1e-5f) * g2[c0];
        float cA = be2[c0] - m2[c0] * aA;
        float aB = rsqrtf(v2[c1] + 1e-5f) * g2[c1];
        float cB = be2[c1] - m2[c1] * aB;
        #pragma unroll
        for (int p = 0; p < P_SEG; p++) {
            float lo, hi;
            UNPACK2(lo, hi, accA[p]);
            s_h2[p*256 + c0] = fmaxf((lo + hi) * aA + cA, 0.0f);
            UNPACK2(lo, hi, accB[p]);
            s_h2[p*256 + c1] = fmaxf((lo + hi) * aB + cB, 0.0f);
        }
    }
    __syncthreads();

    // Stage E: h2 = h2a @ W4 + b4; maxpool + type_emb
    {
        u64 biA, biB; PACK2(biA, b4[c0], 0.0f); PACK2(biB, b4[c1], 0.0f);
        #pragma unroll
        for (int p = 0; p < P_SEG; p++) { accA[p] = biA; accB[p] = biB; }
        for (int k = 0; k < 256; k += 4) {
            float a0 = W4[(k+0)*256 + c0], a1w = W4[(k+1)*256 + c0];
            float a2 = W4[(k+2)*256 + c0], a3 = W4[(k+3)*256 + c0];
            float q0 = W4[(k+0)*256 + c1], q1 = W4[(k+1)*256 + c1];
            float q2 = W4[(k+2)*256 + c1], q3 = W4[(k+3)*256 + c1];
            u64 wa01, wa23, wb01, wb23;
            PACK2(wa01, a0, a1w); PACK2(wa23, a2, a3);
            PACK2(wb01, q0, q1);  PACK2(wb23, q2, q3);
            #pragma unroll
            for (int p = 0; p < P_SEG; p++) {
                ulonglong2 h = *reinterpret_cast<const ulonglong2*>(s_h2 + p*256 + k);
                FMA2(accA[p], h.x, wa01); FMA2(accA[p], h.y, wa23);
                FMA2(accB[p], h.x, wb01); FMA2(accB[p], h.y, wb23);
            }
        }
        float xA = -3.402823466e38f, xB = -3.402823466e38f;
        #pragma unroll
        for (int p = 0; p < P_SEG; p++) {
            float lo, hi;
            UNPACK2(lo, hi, accA[p]); xA = fmaxf(xA, lo + hi);
            UNPACK2(lo, hi, accB[p]); xB = fmaxf(xB, lo + hi);
        }
        int lb = label[idx];
        outF[c0] = xA + temb[lb * 256 + c0];
        outF[c1] = xB + temb[lb * 256 + c1];
    }
}

// ---------------- Kernel 2: positional-embedding MLP, 16 rows/block ---------
// Weights Wp1/Wp2 read once per 16 rows (16x traffic reduction vs fused).
// smem floats: s_pos 32 | s_sine 16*256 | s_pe1 16*512
#define K2_ROWS 16
#define K2_SMEM_FLOATS (32 + K2_ROWS*256 + K2_ROWS*512)

__global__ __launch_bounds__(256, 2)
void map_encoder_pe(const float* __restrict__ tgt,
                    const unsigned int* __restrict__ mask,
                    const float* __restrict__ Wp1, const float* __restrict__ bp1,
                    const float* __restrict__ Wp2, const float* __restrict__ bp2,
                    const float* __restrict__ pcr,
                    float* __restrict__ out)
{
    extern __shared__ float sm[];
    float* s_pos  = sm;                    // 32  (posx,posy per row)
    float* s_sine = s_pos + 32;            // 16*256
    float* s_pe1  = s_sine + K2_ROWS*256;  // 16*512

    const int t    = threadIdx.x;
    const int base = blockIdx.x * K2_ROWS;

    // normalized center coords for the 16 rows
    if (t < 2 * K2_ROWS) {
        int r = t >> 1, ax = t & 1;          // ax: 0=x, 1=y
        float c  = tgt[(size_t)(base + r) * 42 + 20 + ax];
        float lo = pcr[ax], hi = pcr[3 + ax];
        s_pos[t] = (c - lo) / (hi - lo);
    }
    __syncthreads();

    // sine embedding: cols 0..127 from y, 128..255 from x
    for (int i = t; i < K2_ROWS * 256; i += 256) {
        int r = i >> 8, c = i & 255;
        int il = c & 127, j = il >> 1;
        float posv = (c < 128) ? s_pos[2*r + 1] : s_pos[2*r];
        float a = posv * 6.283185307179586f * exp2f(-0.20762050593046014f * (float)j);
        s_sine[i] = (il & 1) ? cosf(a) : sinf(a);
    }
    __syncthreads();

    // pe1 = relu(sine @ Wp1 + bp1): thread owns cols t and t+256 for all 16 rows
    {
        u64 a[K2_ROWS], b[K2_ROWS];
        u64 biA, biB; PACK2(biA, bp1[t], 0.0f); PACK2(biB, bp1[t + 256], 0.0f);
        #pragma unroll
        for (int r = 0; r < K2_ROWS; r++) { a[r] = biA; b[r] = biB; }
        for (int k = 0; k < 256; k += 4) {
            float x0 = Wp1[(k+0)*512 + t],       x1 = Wp1[(k+1)*512 + t];
            float x2 = Wp1[(k+2)*512 + t],       x3 = Wp1[(k+3)*512 + t];
            float y0 = Wp1[(k+0)*512 + t + 256], y1 = Wp1[(k+1)*512 + t + 256];
            float y2 = Wp1[(k+2)*512 + t + 256], y3 = Wp1[(k+3)*512 + t + 256];
            u64 wa01, wa23, wb01, wb23;
            PACK2(wa01, x0, x1); PACK2(wa23, x2, x3);
            PACK2(wb01, y0, y1); PACK2(wb23, y2, y3);
            #pragma unroll
            for (int r = 0; r < K2_ROWS; r++) {
                ulonglong2 sv = *reinterpret_cast<const ulonglong2*>(s_sine + r*256 + k);
                FMA2(a[r], sv.x, wa01); FMA2(a[r], sv.y, wa23);
                FMA2(b[r], sv.x, wb01); FMA2(b[r], sv.y, wb23);
            }
        }
        #pragma unroll
        for (int r = 0; r < K2_ROWS; r++) {
            float lo, hi;
            UNPACK2(lo, hi, a[r]); s_pe1[r*512 + t]       = fmaxf(lo + hi, 0.0f);
            UNPACK2(lo, hi, b[r]); s_pe1[r*512 + t + 256] = fmaxf(lo + hi, 0.0f);
        }
    }
    __syncthreads();

    // pe = pe1 @ Wp2 + bp2: thread owns col t for all 16 rows
    {
        u64 a[K2_ROWS];
        u64 bi; PACK2(bi, bp2[t], 0.0f);
        #pragma unroll
        for (int r = 0; r < K2_ROWS; r++) a[r] = bi;
        for (int k = 0; k < 512; k += 4) {
            float w0 = Wp2[(k+0)*256 + t], w1 = Wp2[(k+1)*256 + t];
            float w2 = Wp2[(k+2)*256 + t], w3 = Wp2[(k+3)*256 + t];
            u64 w01, w23; PACK2(w01, w0, w1); PACK2(w23, w2, w3);
            #pragma unroll
            for (int r = 0; r < K2_ROWS; r++) {
                ulonglong2 pv = *reinterpret_cast<const ulonglong2*>(s_pe1 + r*512 + k);
                FMA2(a[r], pv.x, w01); FMA2(a[r], pv.y, w23);
            }
        }
        #pragma unroll
        for (int r = 0; r < K2_ROWS; r++) {
            int row = base + r;
            float lo, hi; UNPACK2(lo, hi, a[r]);
            float v = (mask[row] != 0u) ? (lo + hi) : 0.0f;
            out[BND + (size_t)row * 256 + t] = v;
        }
    }
}

extern "C" void kernel_launch(void* const* d_in, const int* in_sizes, int n_in,
                              void* d_out, int out_size)
{
    const float*        tgt   = (const float*)d_in[0];
    const int*          label = (const int*)d_in[1];
    const unsigned int* mask  = (const unsigned int*)d_in[2];
    const float* W1  = (const float*)d_in[3];
    const float* b1  = (const float*)d_in[4];
    const float* g1  = (const float*)d_in[5];
    const float* be1 = (const float*)d_in[6];
    const float* m1  = (const float*)d_in[7];
    const float* v1  = (const float*)d_in[8];
    const float* W2  = (const float*)d_in[9];
    const float* b2  = (const float*)d_in[10];
    const float* W3  = (const float*)d_in[11];
    const float* b3  = (const float*)d_in[12];
    const float* g2  = (const float*)d_in[13];
    const float* be2 = (const float*)d_in[14];
    const float* m2  = (const float*)d_in[15];
    const float* v2  = (const float*)d_in[16];
    const float* W4  = (const float*)d_in[17];
    const float* b4  = (const float*)d_in[18];
    const float* te  = (const float*)d_in[19];
    const float* Wp1 = (const float*)d_in[20];
    const float* bp1 = (const float*)d_in[21];
    const float* Wp2 = (const float*)d_in[22];
    const float* bp2 = (const float*)d_in[23];
    const float* pcr = (const float*)d_in[24];
    float* out = (float*)d_out;

    const size_t smem1 = K1_SMEM_FLOATS * sizeof(float);   // 52,704 B
    const size_t smem2 = K2_SMEM_FLOATS * sizeof(float);   // 49,280 B
    cudaFuncSetAttribute(map_encoder_main,
                         cudaFuncAttributeMaxDynamicSharedMemorySize, (int)smem1);
    cudaFuncSetAttribute(map_encoder_pe,
                         cudaFuncAttributeMaxDynamicSharedMemorySize, (int)smem2);

    map_encoder_main<<<BN_TOTAL, 128, smem1>>>(
        tgt, label, mask,
        W1, b1, g1, be1, m1, v1,
        W2, b2, W3, b3, g2, be2, m2, v2,
        W4, b4, te, out);

    map_encoder_pe<<<BN_TOTAL / K2_ROWS, 256, smem2>>>(
        tgt, mask, Wp1, bp1, Wp2, bp2, pcr, out);
}